// round 12
// baseline (speedup 1.0000x reference)
#include <cuda_runtime.h>

typedef unsigned long long u64;

#define BATCH  32768
#define SEQT   28
#define DIMI   32
#define HH     32
#define NSTEPS 10

// ---------- packed f32x2 helpers (sm_103a) ----------
__device__ __forceinline__ u64 ffma2(u64 a, u64 b, u64 c) {
    u64 d;
    asm("fma.rn.f32x2 %0, %1, %2, %3;" : "=l"(d) : "l"(a), "l"(b), "l"(c));
    return d;
}
__device__ __forceinline__ u64 pack2(float a, float b) {
    u64 d;
    asm("mov.b64 %0, {%1, %2};" : "=l"(d) : "f"(a), "f"(b));
    return d;
}
__device__ __forceinline__ void unpack2(u64 a, float& lo, float& hi) {
    asm("mov.b64 {%0, %1}, %2;" : "=f"(lo), "=f"(hi) : "l"(a));
}
__device__ __forceinline__ float hsum2(u64 a) {
    float lo, hi; unpack2(a, lo, hi);
    return lo + hi;
}

// MUFU.EX2-based transcendentals (~1e-7 rel err)
__device__ __forceinline__ float fast_tanh(float x) {
    float e = __expf(2.0f * x);
    return 1.0f - __fdividef(2.0f, e + 1.0f);
}
__device__ __forceinline__ float fast_sigmoid(float x) {
    return __fdividef(1.0f, 1.0f + __expf(-x));
}

struct __align__(16) SW {
    float W1[HH * HH];
    float W2[HH * HH];
    float b1[HH];
    float b2[HH];
    float Wih[3 * HH * DIMI];
    float Whh[3 * HH * HH];
    float bih[3 * HH];
    float bhh[3 * HH];
};

// Dual-row, 4-way k-split matvec with XOR-grouped immediate butterfly.
// Lane quarter q owns input slice k in [8q, 8q+8) (va*/vb* = 4 u64 = 8 floats
// per row). For each output index i (0..7), the lane computes partials of the
// 4 outputs j = 8*(q^g)+i over its k-slice, then a 2-stage shfl_xor butterfly
// yields the FULL dot of the lane's own output j = 8q+i. Partials live only
// inside one i-iteration -> small register footprint.
// FUSE: accumulate a second matvec (vb @ Wb) into the same partials (GRU r/z).
// unroll 4 is load-bearing (ptxas load-hoisting; R8 vs R2/R5/R6/R7 evidence).
template <bool FUSE>
__device__ __forceinline__ void mvq(
    const u64* __restrict__ va0, const u64* __restrict__ va1,
    const float* __restrict__ Wa,
    const u64* __restrict__ vb0, const u64* __restrict__ vb1,
    const float* __restrict__ Wb,
    int q, float* __restrict__ o0, float* __restrict__ o1)
{
    const int q8 = 8 * q;
#pragma unroll 4
    for (int i = 0; i < 8; i++) {
        float p0[4], p1[4];
#pragma unroll
        for (int g = 0; g < 4; g++) {
            const int j = 8 * (q ^ g) + i;
            const ulonglong2* ra = (const ulonglong2*)(Wa + j * HH + q8);
            ulonglong2 w0 = ra[0], w1 = ra[1];
            u64 s0 = ffma2(va0[1], w0.y, ffma2(va0[0], w0.x, 0ull));
            s0 = ffma2(va0[3], w1.y, ffma2(va0[2], w1.x, s0));
            u64 s1 = ffma2(va1[1], w0.y, ffma2(va1[0], w0.x, 0ull));
            s1 = ffma2(va1[3], w1.y, ffma2(va1[2], w1.x, s1));
            if (FUSE) {
                const ulonglong2* rb = (const ulonglong2*)(Wb + j * HH + q8);
                ulonglong2 u0 = rb[0], u1 = rb[1];
                s0 = ffma2(vb0[1], u0.y, ffma2(vb0[0], u0.x, s0));
                s0 = ffma2(vb0[3], u1.y, ffma2(vb0[2], u1.x, s0));
                s1 = ffma2(vb1[1], u0.y, ffma2(vb1[0], u0.x, s1));
                s1 = ffma2(vb1[3], u1.y, ffma2(vb1[2], u1.x, s1));
            }
            p0[g] = hsum2(s0);
            p1[g] = hsum2(s1);
        }
        // butterfly: own output j = 8q+i
        float a01 = p0[0] + __shfl_xor_sync(0xffffffffu, p0[1], 1);
        float a23 = p0[2] + __shfl_xor_sync(0xffffffffu, p0[3], 1);
        o0[i] = a01 + __shfl_xor_sync(0xffffffffu, a23, 2);
        float c01 = p1[0] + __shfl_xor_sync(0xffffffffu, p1[1], 1);
        float c23 = p1[2] + __shfl_xor_sync(0xffffffffu, p1[3], 1);
        o1[i] = c01 + __shfl_xor_sync(0xffffffffu, c23, 2);
    }
}

// ---------- RK4 over one span, dual-row packed state (own 8 elems) ----------
__device__ __forceinline__ void rk4(u64* __restrict__ y0, u64* __restrict__ y1,
                                    float dt, int q, const SW& s) {
    const float dt6 = dt * (1.0f / 6.0f);
    const float dt3 = dt * (1.0f / 3.0f);
    const float dth = dt * 0.5f;
    const float* b1q = s.b1 + 8 * q;
    const float* b2q = s.b2 + 8 * q;
#pragma unroll 1
    for (int st = 0; st < NSTEPS; st++) {
        u64 acc0[4], acc1[4], yt0[4], yt1[4];
#pragma unroll
        for (int p = 0; p < 4; p++) {
            acc0[p] = y0[p]; yt0[p] = y0[p];
            acc1[p] = y1[p]; yt1[p] = y1[p];
        }
#pragma unroll 1
        for (int sidx = 0; sidx < 4; sidx++) {
            const float ca = (sidx == 1 || sidx == 2) ? dt3 : dt6;
            const float cy = (sidx >= 2) ? dt : dth;
            const u64 cap = pack2(ca, ca);
            const u64 cyp = pack2(cy, cy);
            float t0[8], t1[8];
            mvq<false>(yt0, yt1, s.W1, 0, 0, 0, q, t0, t1);
            u64 tp0[4], tp1[4];
#pragma unroll
            for (int p = 0; p < 4; p++) {
                tp0[p] = pack2(fast_tanh(t0[2 * p] + b1q[2 * p]),
                               fast_tanh(t0[2 * p + 1] + b1q[2 * p + 1]));
                tp1[p] = pack2(fast_tanh(t1[2 * p] + b1q[2 * p]),
                               fast_tanh(t1[2 * p + 1] + b1q[2 * p + 1]));
            }
            mvq<false>(tp0, tp1, s.W2, 0, 0, 0, q, t0, t1);
#pragma unroll
            for (int p = 0; p < 4; p++) {
                u64 k0 = pack2(t0[2 * p] + b2q[2 * p], t0[2 * p + 1] + b2q[2 * p + 1]);
                u64 k1 = pack2(t1[2 * p] + b2q[2 * p], t1[2 * p + 1] + b2q[2 * p + 1]);
                acc0[p] = ffma2(cap, k0, acc0[p]);
                yt0[p]  = ffma2(cyp, k0, y0[p]);   // dead at sidx==3
                acc1[p] = ffma2(cap, k1, acc1[p]);
                yt1[p]  = ffma2(cyp, k1, y1[p]);
            }
        }
#pragma unroll
        for (int p = 0; p < 4; p++) { y0[p] = acc0[p]; y1[p] = acc1[p]; }
    }
}

// ---------- GRU cell (PyTorch gate order r,z,n), dual-row ----------
__device__ __forceinline__ void gru(u64* __restrict__ h0, u64* __restrict__ h1,
                                    const float* __restrict__ xg0,
                                    const float* __restrict__ xg1,
                                    int q, const SW& s) {
    const int q8 = 8 * q;
    u64 x0[4], x1[4];
    {
        const ulonglong2* a = (const ulonglong2*)xg0;
        const ulonglong2* b = (const ulonglong2*)xg1;
        ulonglong2 va = a[0], vb = a[1];
        x0[0] = va.x; x0[1] = va.y; x0[2] = vb.x; x0[3] = vb.y;
        va = b[0]; vb = b[1];
        x1[0] = va.x; x1[1] = va.y; x1[2] = vb.x; x1[3] = vb.y;
    }
    float r0[8], r1[8], z0[8], z1[8];

    // r gate: fused x- and h-matvec, single butterfly
    mvq<true>(x0, x1, s.Wih, h0, h1, s.Whh, q, r0, r1);
#pragma unroll
    for (int i = 0; i < 8; i++) {
        float bb = s.bih[q8 + i] + s.bhh[q8 + i];
        r0[i] = fast_sigmoid(r0[i] + bb);
        r1[i] = fast_sigmoid(r1[i] + bb);
    }

    // z gate
    mvq<true>(x0, x1, s.Wih + HH * DIMI, h0, h1, s.Whh + HH * HH, q, z0, z1);
#pragma unroll
    for (int i = 0; i < 8; i++) {
        float bb = s.bih[HH + q8 + i] + s.bhh[HH + q8 + i];
        z0[i] = fast_sigmoid(z0[i] + bb);
        z1[i] = fast_sigmoid(z1[i] + bb);
    }

    // n gate: gi (x-path) and gh (h-path) separate
    float gi0[8], gi1[8], gh0[8], gh1[8];
    mvq<false>(x0, x1, s.Wih + 2 * HH * DIMI, 0, 0, 0, q, gi0, gi1);
    mvq<false>(h0, h1, s.Whh + 2 * HH * HH, 0, 0, 0, q, gh0, gh1);
#pragma unroll
    for (int p = 0; p < 4; p++) {
        float ha, hb; float o[2];
        unpack2(h0[p], ha, hb);
#pragma unroll
        for (int qq = 0; qq < 2; qq++) {
            int i = 2 * p + qq;
            float hn = gh0[i] + s.bhh[2 * HH + q8 + i];
            float n  = fast_tanh(gi0[i] + s.bih[2 * HH + q8 + i] + r0[i] * hn);
            float hv = qq ? hb : ha;
            o[qq] = (1.0f - z0[i]) * n + z0[i] * hv;
        }
        h0[p] = pack2(o[0], o[1]);
        unpack2(h1[p], ha, hb);
#pragma unroll
        for (int qq = 0; qq < 2; qq++) {
            int i = 2 * p + qq;
            float hn = gh1[i] + s.bhh[2 * HH + q8 + i];
            float n  = fast_tanh(gi1[i] + s.bih[2 * HH + q8 + i] + r1[i] * hn);
            float hv = qq ? hb : ha;
            o[qq] = (1.0f - z1[i]) * n + z1[i] * hv;
        }
        h1[p] = pack2(o[0], o[1]);
    }
}

__device__ __forceinline__ void store_relu(float* __restrict__ dst,
                                           const u64* __restrict__ yp) {
#pragma unroll
    for (int p = 0; p < 4; p++) {
        float a, b; unpack2(yp[p], a, b);
        ((float2*)dst)[p] = make_float2(fmaxf(a, 0.0f), fmaxf(b, 0.0f));
    }
}

__global__ void __launch_bounds__(64) ode_gru_kernel(
    const float* __restrict__ inputs,   // [B, 28, 32]
    const float* __restrict__ h0in,     // [B, 32]
    const float* __restrict__ Wih, const float* __restrict__ Whh,
    const float* __restrict__ bih, const float* __restrict__ bhh,
    const float* __restrict__ W1,  const float* __restrict__ b1,
    const float* __restrict__ W2,  const float* __restrict__ b2,
    float* __restrict__ out)            // [2, B, 32]
{
    __shared__ SW s;
    const int tid = threadIdx.x;

    for (int i = tid; i < HH * HH; i += 64) { s.W1[i] = W1[i]; s.W2[i] = W2[i]; }
    for (int i = tid; i < 3 * HH * DIMI; i += 64) { s.Wih[i] = Wih[i]; s.Whh[i] = Whh[i]; }
    if (tid < HH) { s.b1[tid] = b1[tid]; s.b2[tid] = b2[tid]; }
    for (int i = tid; i < 3 * HH; i += 64) { s.bih[i] = bih[i]; s.bhh[i] = bhh[i]; }
    __syncthreads();

    const int gt   = blockIdx.x * 64 + tid;   // 4 lanes (k-quarters) per row-pair
    const int pair = gt >> 2;                 // row-pair index
    const int q    = gt & 3;                  // k-quarter: elems [8q, 8q+8)
    const int q8   = 8 * q;
    const int row0 = 2 * pair;
    const int row1 = 2 * pair + 1;

    u64 y0[4], y1[4];
    {
        const ulonglong2* a = (const ulonglong2*)(h0in + (size_t)row0 * HH + q8);
        const ulonglong2* b = (const ulonglong2*)(h0in + (size_t)row1 * HH + q8);
        ulonglong2 va = a[0], vb = a[1];
        y0[0] = va.x; y0[1] = va.y; y0[2] = vb.x; y0[3] = vb.y;
        va = b[0]; vb = b[1];
        y1[0] = va.x; y1[1] = va.y; y1[2] = vb.x; y1[3] = vb.y;
    }

    const float* xb0 = inputs + (size_t)row0 * SEQT * DIMI + q8;
    const float* xb1 = inputs + (size_t)row1 * SEQT * DIMI + q8;

    rk4(y0, y1, 0.1f, q, s);                      // initial span [0,1]
#pragma unroll 1
    for (int t = 0; t < SEQT - 1; t++) {          // steps 0..26
        gru(y0, y1, xb0 + t * DIMI, xb1 + t * DIMI, q, s);
        rk4(y0, y1, 0.1f, q, s);
    }
    // step 27: GRU -> h_start, then span-14 integration -> h_end
    gru(y0, y1, xb0 + (SEQT - 1) * DIMI, xb1 + (SEQT - 1) * DIMI, q, s);
    store_relu(out + (size_t)row0 * HH + q8, y0);
    store_relu(out + (size_t)row1 * HH + q8, y1);
    rk4(y0, y1, 1.4f, q, s);
    store_relu(out + ((size_t)BATCH + row0) * HH + q8, y0);
    store_relu(out + ((size_t)BATCH + row1) * HH + q8, y1);
}

extern "C" void kernel_launch(void* const* d_in, const int* in_sizes, int n_in,
                              void* d_out, int out_size) {
    (void)in_sizes; (void)n_in; (void)out_size;
    ode_gru_kernel<<<(2 * BATCH) / 64, 64>>>(
        (const float*)d_in[0], (const float*)d_in[1],
        (const float*)d_in[2], (const float*)d_in[3],
        (const float*)d_in[4], (const float*)d_in[5],
        (const float*)d_in[6], (const float*)d_in[7],
        (const float*)d_in[8], (const float*)d_in[9],
        (float*)d_out);
}

// round 13
// speedup vs baseline: 1.5826x; 1.5826x over previous
#include <cuda_runtime.h>

typedef unsigned long long u64;

#define BATCH  32768
#define SEQT   28
#define DIMI   32
#define HH     32
#define NSTEPS 10

// ---------- packed f32x2 helpers (sm_103a) ----------
__device__ __forceinline__ u64 ffma2(u64 a, u64 b, u64 c) {
    u64 d;
    asm("fma.rn.f32x2 %0, %1, %2, %3;" : "=l"(d) : "l"(a), "l"(b), "l"(c));
    return d;
}
__device__ __forceinline__ u64 fadd2(u64 a, u64 b) {
    u64 d;
    asm("add.rn.f32x2 %0, %1, %2;" : "=l"(d) : "l"(a), "l"(b));
    return d;
}
__device__ __forceinline__ u64 pack2(float a, float b) {
    u64 d;
    asm("mov.b64 %0, {%1, %2};" : "=l"(d) : "f"(a), "f"(b));
    return d;
}
__device__ __forceinline__ void unpack2(u64 a, float& lo, float& hi) {
    asm("mov.b64 {%0, %1}, %2;" : "=f"(lo), "=f"(hi) : "l"(a));
}
__device__ __forceinline__ float hsum2(u64 a) {
    float lo, hi; unpack2(a, lo, hi);
    return lo + hi;
}

// Hardware tanh (sm_75+ MUFU.TANH, single op, ~1e-4 rel err)
__device__ __forceinline__ float fast_tanh(float x) {
    float y;
    asm("tanh.approx.f32 %0, %1;" : "=f"(y) : "f"(x));
    return y;
}
// sigmoid(x) = 0.5*tanh(x/2) + 0.5  (1 MUFU + 2 FMA)
__device__ __forceinline__ float fast_sigmoid(float x) {
    return fmaf(0.5f, fast_tanh(0.5f * x), 0.5f);
}

struct __align__(16) SW {
    float W1[HH * HH];
    float W2[HH * HH];
    float b1[HH];
    float b2[HH];
    float Wih[3 * HH * DIMI];
    float Whh[3 * HH * HH];
    float bih[3 * HH];
    float bhh[3 * HH];
};

// Dual-row packed matvec with immediate per-output combine.
// v0/v1: 8 f32x2 pairs each = the lane's 16 k-elems of rows 0/1.
// Each weight LDS.128 feeds BOTH rows' FFMA2 chains (halves LDS per row).
// r0[i]/r1[i] (+)= full dot of output j = q16+i (combined via shfl_xor
// inside the i-iteration, so no long-lived partial arrays).
// unroll 4 is load-bearing (ptxas load-hoisting; see R8 vs R2/R5/R6/R7).
template <bool ACC>
__device__ __forceinline__ void mv2(const u64* __restrict__ v0,
                                    const u64* __restrict__ v1,
                                    const float* __restrict__ Wbase,
                                    int q16,
                                    float* __restrict__ r0,
                                    float* __restrict__ r1) {
    const int jB = 16 - q16;
#pragma unroll 4
    for (int i = 0; i < 16; i++) {
        const ulonglong2* rA = (const ulonglong2*)(Wbase + (q16 + i) * HH + q16);
        const ulonglong2* rB = (const ulonglong2*)(Wbase + (jB + i) * HH + q16);
        u64 a0 = 0ull, a1 = 0ull, b0 = 0ull, b1 = 0ull;
        u64 c0 = 0ull, c1 = 0ull, d0 = 0ull, d1 = 0ull;
#pragma unroll
        for (int c = 0; c < 4; c++) {
            ulonglong2 wa = rA[c];
            ulonglong2 wb = rB[c];
            a0 = ffma2(v0[2 * c],     wa.x, a0);
            a1 = ffma2(v0[2 * c + 1], wa.y, a1);
            b0 = ffma2(v0[2 * c],     wb.x, b0);
            b1 = ffma2(v0[2 * c + 1], wb.y, b1);
            c0 = ffma2(v1[2 * c],     wa.x, c0);
            c1 = ffma2(v1[2 * c + 1], wa.y, c1);
            d0 = ffma2(v1[2 * c],     wb.x, d0);
            d1 = ffma2(v1[2 * c + 1], wb.y, d1);
        }
        float sA0 = hsum2(fadd2(a0, a1));
        float sB0 = hsum2(fadd2(b0, b1));
        float sA1 = hsum2(fadd2(c0, c1));
        float sB1 = hsum2(fadd2(d0, d1));
        float f0 = sA0 + __shfl_xor_sync(0xffffffffu, sB0, 1);
        float f1 = sA1 + __shfl_xor_sync(0xffffffffu, sB1, 1);
        if (ACC) { r0[i] += f0; r1[i] += f1; }
        else     { r0[i] = f0;  r1[i] = f1; }
    }
}

// ---------- RK4 over one span, dual-row packed state ----------
__device__ __forceinline__ void rk4(u64* __restrict__ y0, u64* __restrict__ y1,
                                    float dt, int q16, const SW& s) {
    const float dt6 = dt * (1.0f / 6.0f);
    const float dt3 = dt * (1.0f / 3.0f);
    const float dth = dt * 0.5f;
    const float* b1q = s.b1 + q16;
    const float* b2q = s.b2 + q16;
#pragma unroll 1
    for (int st = 0; st < NSTEPS; st++) {
        u64 acc0[8], acc1[8], yt0[8], yt1[8];
#pragma unroll
        for (int p = 0; p < 8; p++) {
            acc0[p] = y0[p]; yt0[p] = y0[p];
            acc1[p] = y1[p]; yt1[p] = y1[p];
        }
#pragma unroll 1
        for (int sidx = 0; sidx < 4; sidx++) {
            const float ca = (sidx == 1 || sidx == 2) ? dt3 : dt6;
            const float cy = (sidx >= 2) ? dt : dth;
            const u64 cap = pack2(ca, ca);
            const u64 cyp = pack2(cy, cy);
            float t0[16], t1[16];
            mv2<false>(yt0, yt1, s.W1, q16, t0, t1);
            u64 tp0[8], tp1[8];
#pragma unroll
            for (int p = 0; p < 8; p++) {
                tp0[p] = pack2(fast_tanh(t0[2 * p] + b1q[2 * p]),
                               fast_tanh(t0[2 * p + 1] + b1q[2 * p + 1]));
                tp1[p] = pack2(fast_tanh(t1[2 * p] + b1q[2 * p]),
                               fast_tanh(t1[2 * p + 1] + b1q[2 * p + 1]));
            }
            mv2<false>(tp0, tp1, s.W2, q16, t0, t1);
#pragma unroll
            for (int p = 0; p < 8; p++) {
                u64 k0 = pack2(t0[2 * p] + b2q[2 * p], t0[2 * p + 1] + b2q[2 * p + 1]);
                u64 k1 = pack2(t1[2 * p] + b2q[2 * p], t1[2 * p + 1] + b2q[2 * p + 1]);
                acc0[p] = ffma2(cap, k0, acc0[p]);
                yt0[p]  = ffma2(cyp, k0, y0[p]);   // dead at sidx==3
                acc1[p] = ffma2(cap, k1, acc1[p]);
                yt1[p]  = ffma2(cyp, k1, y1[p]);
            }
        }
#pragma unroll
        for (int p = 0; p < 8; p++) { y0[p] = acc0[p]; y1[p] = acc1[p]; }
    }
}

// ---------- GRU cell (PyTorch gate order r,z,n), dual-row ----------
__device__ __forceinline__ void gru(u64* __restrict__ h0, u64* __restrict__ h1,
                                    const float* __restrict__ xg0,
                                    const float* __restrict__ xg1,
                                    int q16, const SW& s) {
    u64 x0[8], x1[8];
    {
        const ulonglong2* a = (const ulonglong2*)xg0;
        const ulonglong2* b = (const ulonglong2*)xg1;
#pragma unroll
        for (int c = 0; c < 4; c++) {
            ulonglong2 va = a[c], vb = b[c];
            x0[2 * c] = va.x; x0[2 * c + 1] = va.y;
            x1[2 * c] = vb.x; x1[2 * c + 1] = vb.y;
        }
    }
    float r0[16], r1[16], z0[16], z1[16];

    // r gate: accumulate x- and h-matvecs, then sigmoid
    mv2<false>(x0, x1, s.Wih, q16, r0, r1);
    mv2<true>(h0, h1, s.Whh, q16, r0, r1);
#pragma unroll
    for (int i = 0; i < 16; i++) {
        float bb = s.bih[q16 + i] + s.bhh[q16 + i];
        r0[i] = fast_sigmoid(r0[i] + bb);
        r1[i] = fast_sigmoid(r1[i] + bb);
    }

    // z gate
    mv2<false>(x0, x1, s.Wih + HH * DIMI, q16, z0, z1);
    mv2<true>(h0, h1, s.Whh + HH * HH, q16, z0, z1);
#pragma unroll
    for (int i = 0; i < 16; i++) {
        float bb = s.bih[HH + q16 + i] + s.bhh[HH + q16 + i];
        z0[i] = fast_sigmoid(z0[i] + bb);
        z1[i] = fast_sigmoid(z1[i] + bb);
    }

    // n gate: gi (x-path) and gh (h-path) kept separate
    float gi0[16], gi1[16], gh0[16], gh1[16];
    mv2<false>(x0, x1, s.Wih + 2 * HH * DIMI, q16, gi0, gi1);
    mv2<false>(h0, h1, s.Whh + 2 * HH * HH, q16, gh0, gh1);
#pragma unroll
    for (int p = 0; p < 8; p++) {
        float ha, hb; float o[2];
        unpack2(h0[p], ha, hb);
#pragma unroll
        for (int qq = 0; qq < 2; qq++) {
            int i = 2 * p + qq;
            float hn = gh0[i] + s.bhh[2 * HH + q16 + i];
            float n  = fast_tanh(gi0[i] + s.bih[2 * HH + q16 + i] + r0[i] * hn);
            float hv = qq ? hb : ha;
            o[qq] = (1.0f - z0[i]) * n + z0[i] * hv;
        }
        h0[p] = pack2(o[0], o[1]);
        unpack2(h1[p], ha, hb);
#pragma unroll
        for (int qq = 0; qq < 2; qq++) {
            int i = 2 * p + qq;
            float hn = gh1[i] + s.bhh[2 * HH + q16 + i];
            float n  = fast_tanh(gi1[i] + s.bih[2 * HH + q16 + i] + r1[i] * hn);
            float hv = qq ? hb : ha;
            o[qq] = (1.0f - z1[i]) * n + z1[i] * hv;
        }
        h1[p] = pack2(o[0], o[1]);
    }
}

__device__ __forceinline__ void store_relu(float* __restrict__ dst,
                                           const u64* __restrict__ yp) {
#pragma unroll
    for (int p = 0; p < 8; p++) {
        float a, b; unpack2(yp[p], a, b);
        ((float2*)dst)[p] = make_float2(fmaxf(a, 0.0f), fmaxf(b, 0.0f));
    }
}

__global__ void __launch_bounds__(64) ode_gru_kernel(
    const float* __restrict__ inputs,   // [B, 28, 32]
    const float* __restrict__ h0in,     // [B, 32]
    const float* __restrict__ Wih, const float* __restrict__ Whh,
    const float* __restrict__ bih, const float* __restrict__ bhh,
    const float* __restrict__ W1,  const float* __restrict__ b1,
    const float* __restrict__ W2,  const float* __restrict__ b2,
    float* __restrict__ out)            // [2, B, 32]
{
    __shared__ SW s;
    const int tid = threadIdx.x;

    for (int i = tid; i < HH * HH; i += 64) { s.W1[i] = W1[i]; s.W2[i] = W2[i]; }
    for (int i = tid; i < 3 * HH * DIMI; i += 64) { s.Wih[i] = Wih[i]; s.Whh[i] = Whh[i]; }
    if (tid < HH) { s.b1[tid] = b1[tid]; s.b2[tid] = b2[tid]; }
    for (int i = tid; i < 3 * HH; i += 64) { s.bih[i] = bih[i]; s.bhh[i] = bhh[i]; }
    __syncthreads();

    const int gt   = blockIdx.x * 64 + tid;   // 2 lanes per row-pair
    const int pair = gt >> 1;                 // row-pair index
    const int q16  = (gt & 1) * 16;           // lane's element-half offset
    const int row0 = 2 * pair;
    const int row1 = 2 * pair + 1;

    u64 y0[8], y1[8];
    {
        const ulonglong2* a = (const ulonglong2*)(h0in + (size_t)row0 * HH + q16);
        const ulonglong2* b = (const ulonglong2*)(h0in + (size_t)row1 * HH + q16);
#pragma unroll
        for (int c = 0; c < 4; c++) {
            ulonglong2 va = a[c], vb = b[c];
            y0[2 * c] = va.x; y0[2 * c + 1] = va.y;
            y1[2 * c] = vb.x; y1[2 * c + 1] = vb.y;
        }
    }

    const float* xb0 = inputs + (size_t)row0 * SEQT * DIMI + q16;
    const float* xb1 = inputs + (size_t)row1 * SEQT * DIMI + q16;

    rk4(y0, y1, 0.1f, q16, s);                    // initial span [0,1]
#pragma unroll 1
    for (int t = 0; t < SEQT - 1; t++) {          // steps 0..26
        gru(y0, y1, xb0 + t * DIMI, xb1 + t * DIMI, q16, s);
        rk4(y0, y1, 0.1f, q16, s);
    }
    // step 27: GRU -> h_start, then span-14 integration -> h_end
    gru(y0, y1, xb0 + (SEQT - 1) * DIMI, xb1 + (SEQT - 1) * DIMI, q16, s);
    store_relu(out + (size_t)row0 * HH + q16, y0);
    store_relu(out + (size_t)row1 * HH + q16, y1);
    rk4(y0, y1, 1.4f, q16, s);
    store_relu(out + ((size_t)BATCH + row0) * HH + q16, y0);
    store_relu(out + ((size_t)BATCH + row1) * HH + q16, y1);
}

extern "C" void kernel_launch(void* const* d_in, const int* in_sizes, int n_in,
                              void* d_out, int out_size) {
    (void)in_sizes; (void)n_in; (void)out_size;
    ode_gru_kernel<<<BATCH / 64, 64>>>(
        (const float*)d_in[0], (const float*)d_in[1],
        (const float*)d_in[2], (const float*)d_in[3],
        (const float*)d_in[4], (const float*)d_in[5],
        (const float*)d_in[6], (const float*)d_in[7],
        (const float*)d_in[8], (const float*)d_in[9],
        (float*)d_out);
}